// round 7
// baseline (speedup 1.0000x reference)
#include <cuda_runtime.h>
#include <cuda_bf16.h>
#include <cstdint>

static constexpr int Bn = 128;
static constexpr int Sn = 1024;
static constexpr int Dn = 1024;
static constexpr float LOG2F_ = 0.69314718055994530942f;

__device__ double g_pos_acc;
__device__ double g_neg_acc;
__device__ int g_lens[Bn];
__device__ int g_ticket;
__device__ __nv_bfloat16 g_ctx_bf16[Bn * Dn];

// dynamic smem window (1024-aligned), BM=128, BK=64:
//   A32 ring: 3 x 32 KB  (128 rows x 256 B fp32)          [0, 98304)
//   Abf ring: 2 x 16 KB  (128 rows x 128 B bf16, SW128)   [98304, 131072)
//   B   ring: 3 x 16 KB  (128 graphs x 128 B bf16, SW128) [131072, 180224)
__host__ __device__ constexpr uint32_t OFF_A32(int s) { return (uint32_t)s * 32768u; }
__host__ __device__ constexpr uint32_t OFF_ABF(int a) { return 98304u + (uint32_t)a * 16384u; }
__host__ __device__ constexpr uint32_t OFF_B(int s)   { return 131072u + (uint32_t)s * 16384u; }
static constexpr uint32_t SMEM_BYTES = 180224u + 1024u;

// ---------------------------------------------------------------------------
// prep: ctx fp32 -> bf16, lens, zero accumulators + ticket
// ---------------------------------------------------------------------------
__global__ void __launch_bounds__(256) prep_kernel(const float* __restrict__ ctx,
                                                   const int* __restrict__ mask) {
    const int b = blockIdx.x;
    const int tid = threadIdx.x;
    float4 v = reinterpret_cast<const float4*>(ctx + b * Dn)[tid];
    __nv_bfloat162 h0 = __float22bfloat162_rn(make_float2(v.x, v.y));
    __nv_bfloat162 h1 = __float22bfloat162_rn(make_float2(v.z, v.w));
    uint2 packed;
    packed.x = *reinterpret_cast<uint32_t*>(&h0);
    packed.y = *reinterpret_cast<uint32_t*>(&h1);
    reinterpret_cast<uint2*>(g_ctx_bf16 + b * Dn)[tid] = packed;
    int4 m = reinterpret_cast<const int4*>(mask + b * Sn)[tid];
    int s = m.x + m.y + m.z + m.w;
    #pragma unroll
    for (int off = 16; off > 0; off >>= 1)
        s += __shfl_xor_sync(0xffffffffu, s, off);
    __shared__ int wsum[8];
    if ((tid & 31) == 0) wsum[tid >> 5] = s;
    __syncthreads();
    if (tid == 0) {
        int tot = 0;
        #pragma unroll
        for (int i = 0; i < 8; i++) tot += wsum[i];
        g_lens[b] = tot > 0 ? tot : 1;
        if (b == 0) { g_pos_acc = 0.0; g_neg_acc = 0.0; g_ticket = 0; }
    }
}

__device__ __forceinline__ void ldm_x4(uint32_t& r0, uint32_t& r1, uint32_t& r2,
                                       uint32_t& r3, uint32_t addr) {
    asm volatile("ldmatrix.sync.aligned.m8n8.x4.shared.b16 {%0,%1,%2,%3}, [%4];"
                 : "=r"(r0), "=r"(r1), "=r"(r2), "=r"(r3) : "r"(addr));
}

__device__ __forceinline__ void mma_bf16(float* c, const uint32_t* a, const uint32_t* b) {
    asm volatile("mma.sync.aligned.m16n8k16.row.col.f32.bf16.bf16.f32 "
                 "{%0,%1,%2,%3}, {%4,%5,%6,%7}, {%8,%9}, {%0,%1,%2,%3};"
                 : "+f"(c[0]), "+f"(c[1]), "+f"(c[2]), "+f"(c[3])
                 : "r"(a[0]), "r"(a[1]), "r"(a[2]), "r"(a[3]), "r"(b[0]), "r"(b[1]));
}

#define CP_ASYNC16(dst, src) \
    asm volatile("cp.async.cg.shared.global [%0], [%1], 16;" :: "r"(dst), "l"(src))
#define CP_COMMIT() asm volatile("cp.async.commit_group;")
#define CP_WAIT0()  asm volatile("cp.async.wait_group 0;" ::: "memory")
#define CP_WAIT1()  asm volatile("cp.async.wait_group 1;" ::: "memory")

// ---------------------------------------------------------------------------
// main: BM=128 (one b), BN=128, BK=64. 256 threads / 8 warps:
// 4 warp-tile positions of 64x64 (2x2 grid) x 2-way K-split (h = w>>2).
// A streamed as raw fp32 via 3-stage cp.async ring (depth-2 prefetch), then
// on-chip fp32->bf16 convert into double-buffered swizzled Abf. B via 3-stage
// cp.async ring (bf16 staged by prep). K-split partials merged through smem,
// fused JSD epilogue + single-kernel finalize via atomic ticket.
// ---------------------------------------------------------------------------
__global__ void __launch_bounds__(256, 1)
mi_main_kernel(const float* __restrict__ seq, float* __restrict__ out) {
    extern __shared__ __align__(16) uint8_t dynsm_raw[];
    __shared__ float redp[8], redn[8];

    const int tid = threadIdx.x;
    const int lane = tid & 31;
    const int w = tid >> 5;        // 0..7
    const int p = w & 3;           // warp-tile position (2x2)
    const int h = w >> 2;          // k-half: warps 0-3 -> ks{0,1}, 4-7 -> ks{2,3}
    const int wm = p >> 1;         // 2 x 64 rows
    const int wn = p & 1;          // 2 x 64 cols
    const int tok0 = blockIdx.x * 128;
    const int b = tok0 >> 10;
    const int s0 = tok0 & (Sn - 1);

    const uint32_t rawB = (uint32_t)__cvta_generic_to_shared(dynsm_raw);
    const uint32_t sBase = (rawB + 1023u) & ~1023u;
    uint8_t* dynsm = dynsm_raw + (sBase - rawB);

    float acc[4][8][4];
    #pragma unroll
    for (int i = 0; i < 4; i++)
        #pragma unroll
        for (int j = 0; j < 8; j++)
            #pragma unroll
            for (int r = 0; r < 4; r++) acc[i][j][r] = 0.0f;

    // issue one chunk's A (raw fp32) + B (bf16) as a single commit group
    auto issue_chunk = [&](int kb, int s) {
        #pragma unroll
        for (int j = 0; j < 8; j++) {                 // A32: 2048 x 16B / 256 thr
            int fi = tid + j * 256;
            int rw = fi >> 4;
            int fc = fi & 15;
            CP_ASYNC16(sBase + OFF_A32(s) + rw * 256 + fc * 16,
                       seq + (size_t)(tok0 + rw) * Dn + kb * 64 + fc * 4);
        }
        #pragma unroll
        for (int j = 0; j < 4; j++) {                 // B: 1024 x 16B / 256 thr
            int lc = tid + j * 256;
            int rw = lc >> 3;
            int cc = lc & 7;
            uint32_t off = rw * 128 + cc * 16;
            uint32_t sw = off ^ ((off >> 3) & 0x70);
            CP_ASYNC16(sBase + OFF_B(s) + sw, g_ctx_bf16 + rw * Dn + kb * 64 + cc * 8);
        }
        CP_COMMIT();
    };

    // on-chip convert: A32[s] fp32 -> Abf[a] bf16 (SW128 swizzled)
    auto convert = [&](int s, int a) {
        #pragma unroll
        for (int j = 0; j < 8; j++) {
            int fi = tid + j * 256;
            int rw = fi >> 4;
            int fc = fi & 15;
            float4 v = *reinterpret_cast<const float4*>(dynsm + OFF_A32(s) + rw * 256 + fc * 16);
            __nv_bfloat162 h0 = __float22bfloat162_rn(make_float2(v.x, v.y));
            __nv_bfloat162 h1 = __float22bfloat162_rn(make_float2(v.z, v.w));
            uint2 vv;
            vv.x = *reinterpret_cast<uint32_t*>(&h0);
            vv.y = *reinterpret_cast<uint32_t*>(&h1);
            uint32_t off = rw * 128 + fc * 8;
            uint32_t sw = off ^ ((off >> 3) & 0x70);
            *reinterpret_cast<uint2*>(dynsm + OFF_ABF(a) + sw) = vv;
        }
    };

    auto compute_ks = [&](uint32_t aB, uint32_t bB, int ks) {
        uint32_t afr[4][4];
        #pragma unroll
        for (int mf = 0; mf < 4; mf++) {
            int r = wm * 64 + mf * 16 + (lane & 15);
            int ch = ks * 2 + (lane >> 4);
            ldm_x4(afr[mf][0], afr[mf][1], afr[mf][2], afr[mf][3],
                   aB + r * 128 + ((ch ^ (r & 7)) << 4));
        }
        uint32_t bfr[8][2];
        #pragma unroll
        for (int nq = 0; nq < 4; nq++) {
            int r = wn * 64 + nq * 16 + (lane & 7) + ((lane & 16) >> 1);
            int ch = ks * 2 + ((lane >> 3) & 1);
            uint32_t t0, t1, t2, t3;
            ldm_x4(t0, t1, t2, t3, bB + r * 128 + ((ch ^ (r & 7)) << 4));
            bfr[nq * 2][0] = t0; bfr[nq * 2][1] = t1;
            bfr[nq * 2 + 1][0] = t2; bfr[nq * 2 + 1][1] = t3;
        }
        #pragma unroll
        for (int mf = 0; mf < 4; mf++)
            #pragma unroll
            for (int nf = 0; nf < 8; nf++)
                mma_bf16(acc[mf][nf], afr[mf], bfr[nf]);
    };

    // ---- prologue: chunks 0 and 1 in flight; convert chunk 0 ----
    issue_chunk(0, 0);
    issue_chunk(1, 1);
    CP_WAIT1();                 // group 0 complete
    convert(0, 0);
    __syncthreads();

    // ---- mainloop: depth-2 cp.async pipeline, one sync per chunk ----
    for (int kb = 0; kb < 16; kb++) {
        if (kb <= 13) issue_chunk(kb + 2, (kb + 2) % 3);
        const uint32_t aB = sBase + OFF_ABF(kb & 1);
        const uint32_t bB = sBase + OFF_B(kb % 3);
        compute_ks(aB, bB, 2 * h);
        compute_ks(aB, bB, 2 * h + 1);
        if (kb <= 14) {
            if (kb <= 13) CP_WAIT1();   // group kb+1 complete (kb+2 may pend)
            else          CP_WAIT0();
            convert((kb + 1) % 3, (kb + 1) & 1);
        }
        __syncthreads();
    }

    // ---- K-split merge: warps 4-7 dump partials, warps 0-3 add ----
    float* mrg = reinterpret_cast<float*>(dynsm);   // reuse A32 region (64 KB)
    if (h == 1) {
        #pragma unroll
        for (int mf = 0; mf < 4; mf++)
            #pragma unroll
            for (int nf = 0; nf < 8; nf++)
                *reinterpret_cast<float4*>(mrg + p * 4096 + (mf * 8 + nf) * 128 + lane * 4) =
                    make_float4(acc[mf][nf][0], acc[mf][nf][1], acc[mf][nf][2], acc[mf][nf][3]);
    }
    __syncthreads();

    // ---- JSD epilogue (warps 0-3 own the merged tiles) ----
    const int len = g_lens[b];
    float pos = 0.0f, neg = 0.0f;
    if (h == 0) {
        #pragma unroll
        for (int mf = 0; mf < 4; mf++) {
            #pragma unroll
            for (int nf = 0; nf < 8; nf++) {
                float4 o = *reinterpret_cast<const float4*>(
                    mrg + p * 4096 + (mf * 8 + nf) * 128 + lane * 4);
                float vv[4] = {acc[mf][nf][0] + o.x, acc[mf][nf][1] + o.y,
                               acc[mf][nf][2] + o.z, acc[mf][nf][3] + o.w};
                #pragma unroll
                for (int r = 0; r < 4; r++) {
                    int row = wm * 64 + mf * 16 + (lane >> 2) + ((r & 2) ? 8 : 0);
                    int s   = s0 + row;
                    int k   = wn * 64 + nf * 8 + ((lane & 3) << 1) + (r & 1);
                    float v = vv[r];
                    if (s < len) {
                        float sp = fmaxf(-v, 0.0f) + __logf(1.0f + __expf(-fabsf(v)));
                        if (k == b) pos += LOG2F_ - sp;
                        else        neg += sp + v - LOG2F_;
                    }
                }
            }
        }
    }
    #pragma unroll
    for (int off = 16; off > 0; off >>= 1) {
        pos += __shfl_xor_sync(0xffffffffu, pos, off);
        neg += __shfl_xor_sync(0xffffffffu, neg, off);
    }
    if (lane == 0) { redp[w] = pos; redn[w] = neg; }
    __syncthreads();
    if (tid == 0) {
        double pp = 0.0, nn = 0.0;
        #pragma unroll
        for (int i = 0; i < 8; i++) { pp += (double)redp[i]; nn += (double)redn[i]; }
        atomicAdd(&g_pos_acc, pp);
        atomicAdd(&g_neg_acc, nn);
        __threadfence();
        int old = atomicAdd(&g_ticket, 1);
        if (old == (int)gridDim.x - 1) {
            double tot = 0.0;
            for (int i = 0; i < Bn; i++) tot += (double)g_lens[i];
            double P = atomicAdd(&g_pos_acc, 0.0);
            double N = atomicAdd(&g_neg_acc, 0.0);
            out[0] = (float)(N / (tot * (double)(Bn - 1)) - P / tot);
        }
    }
}

extern "C" void kernel_launch(void* const* d_in, const int* in_sizes, int n_in,
                              void* d_out, int out_size) {
    const float* seq  = (const float*)d_in[0];
    const float* ctx  = (const float*)d_in[1];
    const int*   mask = (const int*)d_in[2];
    static bool attr_set = false;
    if (!attr_set) {
        cudaFuncSetAttribute(mi_main_kernel,
                             cudaFuncAttributeMaxDynamicSharedMemorySize, SMEM_BYTES);
        attr_set = true;
    }
    prep_kernel<<<Bn, 256>>>(ctx, mask);
    mi_main_kernel<<<(Bn * Sn) / 128, 256, SMEM_BYTES>>>(seq, (float*)d_out);
}

// round 8
// speedup vs baseline: 1.1075x; 1.1075x over previous
#include <cuda_runtime.h>
#include <cuda_bf16.h>
#include <cstdint>

static constexpr int Bn = 128;
static constexpr int Sn = 1024;
static constexpr int Dn = 1024;
static constexpr float LOG2F_ = 0.69314718055994530942f;

__device__ double g_pos_acc;
__device__ double g_neg_acc;
__device__ int g_lens[Bn];
__device__ int g_ticket;
__device__ __nv_bfloat16 g_ctx_bf16[Bn * Dn];

// dynamic smem (1024-aligned window): B ring, 4 stages x 16 KB (128 x 128B SW128)
__host__ __device__ constexpr uint32_t OFF_B(int s) { return (uint32_t)s * 16384u; }
static constexpr uint32_t SMEM_BYTES = 65536u + 1024u;

// ---------------------------------------------------------------------------
// prep: ctx fp32 -> bf16, lens, zero accumulators + ticket
// ---------------------------------------------------------------------------
__global__ void __launch_bounds__(256) prep_kernel(const float* __restrict__ ctx,
                                                   const int* __restrict__ mask) {
    const int b = blockIdx.x;
    const int tid = threadIdx.x;
    float4 v = reinterpret_cast<const float4*>(ctx + b * Dn)[tid];
    __nv_bfloat162 h0 = __float22bfloat162_rn(make_float2(v.x, v.y));
    __nv_bfloat162 h1 = __float22bfloat162_rn(make_float2(v.z, v.w));
    uint2 packed;
    packed.x = *reinterpret_cast<uint32_t*>(&h0);
    packed.y = *reinterpret_cast<uint32_t*>(&h1);
    reinterpret_cast<uint2*>(g_ctx_bf16 + b * Dn)[tid] = packed;
    int4 m = reinterpret_cast<const int4*>(mask + b * Sn)[tid];
    int s = m.x + m.y + m.z + m.w;
    #pragma unroll
    for (int off = 16; off > 0; off >>= 1)
        s += __shfl_xor_sync(0xffffffffu, s, off);
    __shared__ int wsum[8];
    if ((tid & 31) == 0) wsum[tid >> 5] = s;
    __syncthreads();
    if (tid == 0) {
        int tot = 0;
        #pragma unroll
        for (int i = 0; i < 8; i++) tot += wsum[i];
        g_lens[b] = tot > 0 ? tot : 1;
        if (b == 0) { g_pos_acc = 0.0; g_neg_acc = 0.0; g_ticket = 0; }
    }
}

__device__ __forceinline__ void ldm_x4(uint32_t& r0, uint32_t& r1, uint32_t& r2,
                                       uint32_t& r3, uint32_t addr) {
    asm volatile("ldmatrix.sync.aligned.m8n8.x4.shared.b16 {%0,%1,%2,%3}, [%4];"
                 : "=r"(r0), "=r"(r1), "=r"(r2), "=r"(r3) : "r"(addr));
}

__device__ __forceinline__ void mma_bf16(float* c, const uint32_t* a, const uint32_t* b) {
    asm volatile("mma.sync.aligned.m16n8k16.row.col.f32.bf16.bf16.f32 "
                 "{%0,%1,%2,%3}, {%4,%5,%6,%7}, {%8,%9}, {%0,%1,%2,%3};"
                 : "+f"(c[0]), "+f"(c[1]), "+f"(c[2]), "+f"(c[3])
                 : "r"(a[0]), "r"(a[1]), "r"(a[2]), "r"(a[3]), "r"(b[0]), "r"(b[1]));
}

#define CP_ASYNC16(dst, src) \
    asm volatile("cp.async.cg.shared.global [%0], [%1], 16;" :: "r"(dst), "l"(src))
#define CP_COMMIT() asm volatile("cp.async.commit_group;")
#define CP_WAIT0()  asm volatile("cp.async.wait_group 0;" ::: "memory")
#define CP_WAIT1()  asm volatile("cp.async.wait_group 1;" ::: "memory")
#define CP_WAIT2()  asm volatile("cp.async.wait_group 2;" ::: "memory")

// ---------------------------------------------------------------------------
// main: BM=128 (one b), BN=128, 128 threads / 4 warps, warp tile 32x128.
// A: fp32 LDG.64 DIRECTLY into registers in mma fragment layout (2 k-steps
// ahead), in-register bf16 convert -> no smem/barrier on the A path.
// B: cp.async bf16 ring (4 x 16KB, SW128) + ldmatrix; one sync per chunk.
// 2 CTAs/SM. Fused JSD epilogue + finalize via atomic ticket.
// ---------------------------------------------------------------------------
__global__ void __launch_bounds__(128, 2)
mi_main_kernel(const float* __restrict__ seq, float* __restrict__ out) {
    extern __shared__ __align__(16) uint8_t dynsm_raw[];
    __shared__ float redp[4], redn[4];

    const int tid = threadIdx.x;
    const int lane = tid & 31;
    const int w = tid >> 5;            // 0..3, warp owns rows w*32..w*32+31
    const int tok0 = blockIdx.x * 128;
    const int b = tok0 >> 10;
    const int s0 = tok0 & (Sn - 1);

    const uint32_t rawB = (uint32_t)__cvta_generic_to_shared(dynsm_raw);
    const uint32_t sBase = (rawB + 1023u) & ~1023u;

    float acc[2][16][4];
    #pragma unroll
    for (int i = 0; i < 2; i++)
        #pragma unroll
        for (int j = 0; j < 16; j++)
            #pragma unroll
            for (int r = 0; r < 4; r++) acc[i][j][r] = 0.0f;

    // A fragment prefetch: [slot][mf][j], j: 0=(r,c) 1=(r+8,c) 2=(r,c+8) 3=(r+8,c+8)
    float2 pf[2][2][4];
    const float* aBase = seq + (size_t)(tok0 + w * 32 + (lane >> 2)) * Dn + (lane & 3) * 2;

    auto loadA = [&](int slot, int gks) {
        #pragma unroll
        for (int mf = 0; mf < 2; mf++) {
            const float* p = aBase + (size_t)(mf * 16) * Dn + gks * 16;
            pf[slot][mf][0] = *reinterpret_cast<const float2*>(p);
            pf[slot][mf][1] = *reinterpret_cast<const float2*>(p + 8 * Dn);
            pf[slot][mf][2] = *reinterpret_cast<const float2*>(p + 8);
            pf[slot][mf][3] = *reinterpret_cast<const float2*>(p + 8 * Dn + 8);
        }
    };
    auto issueB = [&](int kb, int s) {
        #pragma unroll
        for (int j = 0; j < 8; j++) {          // 1024 x 16B / 128 threads
            int lc = tid + j * 128;
            int rw = lc >> 3;
            int cc = lc & 7;
            uint32_t off = rw * 128 + cc * 16;
            uint32_t sw = off ^ ((off >> 3) & 0x70);
            CP_ASYNC16(sBase + OFF_B(s) + sw, g_ctx_bf16 + rw * Dn + kb * 64 + cc * 8);
        }
        CP_COMMIT();
    };

    // prologue: B chunks 0..2 in flight; A k-steps 0,1 in regs
    issueB(0, 0);
    issueB(1, 1);
    issueB(2, 2);
    loadA(0, 0);
    loadA(1, 1);
    CP_WAIT2();                     // chunk 0 resident
    __syncthreads();

    for (int kb = 0; kb < 16; kb++) {
        const uint32_t bB = sBase + OFF_B(kb & 3);
        #pragma unroll
        for (int ks = 0; ks < 4; ks++) {
            const int gks = kb * 4 + ks;
            const int slot = gks & 1;
            // convert current A fragment fp32 -> bf16x2
            uint32_t afr[2][4];
            #pragma unroll
            for (int mf = 0; mf < 2; mf++)
                #pragma unroll
                for (int j = 0; j < 4; j++) {
                    __nv_bfloat162 h = __float22bfloat162_rn(
                        make_float2(pf[slot][mf][j].x, pf[slot][mf][j].y));
                    afr[mf][j] = *reinterpret_cast<uint32_t*>(&h);
                }
            // refill slot with k-step gks+2 (regs free after cvt)
            if (gks < 62) loadA(slot, gks + 2);
            // B fragments: 8x ldm_x4 covers all 16 n8-tiles
            uint32_t bfr[16][2];
            #pragma unroll
            for (int nq = 0; nq < 8; nq++) {
                int r = nq * 16 + (lane & 7) + ((lane & 16) >> 1);
                int ch = ks * 2 + ((lane >> 3) & 1);
                uint32_t t0, t1, t2, t3;
                ldm_x4(t0, t1, t2, t3, bB + r * 128 + ((ch ^ (r & 7)) << 4));
                bfr[nq * 2][0] = t0; bfr[nq * 2][1] = t1;
                bfr[nq * 2 + 1][0] = t2; bfr[nq * 2 + 1][1] = t3;
            }
            #pragma unroll
            for (int mf = 0; mf < 2; mf++)
                #pragma unroll
                for (int nf = 0; nf < 16; nf++)
                    mma_bf16(acc[mf][nf], afr[mf], bfr[nf]);
        }
        if (kb + 3 <= 15) issueB(kb + 3, (kb + 3) & 3);
        if (kb < 15) {
            if (kb <= 12)      CP_WAIT2();
            else if (kb == 13) CP_WAIT1();
            else               CP_WAIT0();
            __syncthreads();
        }
    }

    // ---- JSD epilogue: warp owns rows w*32..+31, all 128 cols ----
    const int len = g_lens[b];
    float pos = 0.0f, neg = 0.0f;
    #pragma unroll
    for (int mf = 0; mf < 2; mf++) {
        #pragma unroll
        for (int nf = 0; nf < 16; nf++) {
            #pragma unroll
            for (int r = 0; r < 4; r++) {
                int row = w * 32 + mf * 16 + (lane >> 2) + ((r & 2) ? 8 : 0);
                int s   = s0 + row;
                int k   = nf * 8 + ((lane & 3) << 1) + (r & 1);
                float v = acc[mf][nf][r];
                if (s < len) {
                    float sp = fmaxf(-v, 0.0f) + __logf(1.0f + __expf(-fabsf(v)));
                    if (k == b) pos += LOG2F_ - sp;
                    else        neg += sp + v - LOG2F_;
                }
            }
        }
    }
    #pragma unroll
    for (int off = 16; off > 0; off >>= 1) {
        pos += __shfl_xor_sync(0xffffffffu, pos, off);
        neg += __shfl_xor_sync(0xffffffffu, neg, off);
    }
    if (lane == 0) { redp[w] = pos; redn[w] = neg; }
    __syncthreads();
    if (tid == 0) {
        double pp = (double)redp[0] + redp[1] + redp[2] + redp[3];
        double nn = (double)redn[0] + redn[1] + redn[2] + redn[3];
        atomicAdd(&g_pos_acc, pp);
        atomicAdd(&g_neg_acc, nn);
        __threadfence();
        int old = atomicAdd(&g_ticket, 1);
        if (old == (int)gridDim.x - 1) {
            double tot = 0.0;
            for (int i = 0; i < Bn; i++) tot += (double)g_lens[i];
            double P = atomicAdd(&g_pos_acc, 0.0);
            double N = atomicAdd(&g_neg_acc, 0.0);
            out[0] = (float)(N / (tot * (double)(Bn - 1)) - P / tot);
        }
    }
}

extern "C" void kernel_launch(void* const* d_in, const int* in_sizes, int n_in,
                              void* d_out, int out_size) {
    const float* seq  = (const float*)d_in[0];
    const float* ctx  = (const float*)d_in[1];
    const int*   mask = (const int*)d_in[2];
    static bool attr_set = false;
    if (!attr_set) {
        cudaFuncSetAttribute(mi_main_kernel,
                             cudaFuncAttributeMaxDynamicSharedMemorySize, SMEM_BYTES);
        attr_set = true;
    }
    prep_kernel<<<Bn, 256>>>(ctx, mask);
    mi_main_kernel<<<(Bn * Sn) / 128, 128, SMEM_BYTES>>>(seq, (float*)d_out);
}